// round 1
// baseline (speedup 1.0000x reference)
#include <cuda_runtime.h>
#include <math.h>

#define BATCH   4096
#define D_MODEL 1024
#define NT      64
#define RANK    8
#define NR      (NT * RANK)   /* 512 */

// Scratch (device globals: no allocation allowed in kernel_launch)
__device__ float g_Y[(size_t)BATCH * NR];      // gated Vx, (batch, n*r)
__device__ float g_Wt[(size_t)D_MODEL * NR];   // U transposed: Wt[d][k] = U[n,d,r], k=n*8+r

// ---------------------------------------------------------------------------
// Generic NT GEMM: C[M,N] = A[M,K] @ B[N,K]^T, row-major A and B.
// MODE 0: gate epilogue  v = relu(acc - bias[col]) -> C (gate buffer)
// MODE 1: scale epilogue v = acc * gate[row*NT + col/8] -> g_Y
// MODE 2: plain          A := g_Y, B := g_Wt, write acc -> C
// ---------------------------------------------------------------------------
template <int BM, int BN, int BK, int TM, int TN, int MODE>
__global__ __launch_bounds__((BM / TM) * (BN / TN))
void gemm_nt(const float* __restrict__ A, const float* __restrict__ B,
             float* __restrict__ C, int M, int N, int K,
             const float* __restrict__ bias, const float* __restrict__ gate)
{
    constexpr int THREADS = (BM / TM) * (BN / TN);
    __shared__ float As[BK][BM + 1];
    __shared__ float Bs[BK][BN + 1];

    const int tid  = threadIdx.x;
    const int row0 = blockIdx.y * BM;
    const int col0 = blockIdx.x * BN;
    const int tcol = tid % (BN / TN);
    const int trow = tid / (BN / TN);

    const float* Aptr = A;
    const float* Bptr = B;
    if constexpr (MODE == 2) { Aptr = g_Y; Bptr = g_Wt; }

    float acc[TM][TN];
#pragma unroll
    for (int i = 0; i < TM; i++)
#pragma unroll
        for (int j = 0; j < TN; j++) acc[i][j] = 0.0f;

    for (int k0 = 0; k0 < K; k0 += BK) {
        // Load A tile (BM x BK) transposed into SMEM
#pragma unroll
        for (int i = tid; i < BM * BK; i += THREADS) {
            int m = i / BK, k = i % BK;
            As[k][m] = Aptr[(size_t)(row0 + m) * K + k0 + k];
        }
        // Load B tile (BN x BK) transposed into SMEM
#pragma unroll
        for (int i = tid; i < BN * BK; i += THREADS) {
            int n = i / BK, k = i % BK;
            Bs[k][n] = Bptr[(size_t)(col0 + n) * K + k0 + k];
        }
        __syncthreads();

#pragma unroll
        for (int k = 0; k < BK; k++) {
            float ar[TM], br[TN];
#pragma unroll
            for (int i = 0; i < TM; i++) ar[i] = As[k][trow * TM + i];
#pragma unroll
            for (int j = 0; j < TN; j++) br[j] = Bs[k][tcol * TN + j];
#pragma unroll
            for (int i = 0; i < TM; i++)
#pragma unroll
                for (int j = 0; j < TN; j++) acc[i][j] += ar[i] * br[j];
        }
        __syncthreads();
    }

    // Epilogue
#pragma unroll
    for (int i = 0; i < TM; i++) {
        int row = row0 + trow * TM + i;
#pragma unroll
        for (int j = 0; j < TN; j++) {
            int col = col0 + tcol * TN + j;
            float v = acc[i][j];
            if constexpr (MODE == 0) {
                v -= bias[col];
                v = v > 0.0f ? v : 0.0f;
                C[(size_t)row * N + col] = v;
            } else if constexpr (MODE == 1) {
                v *= gate[(size_t)row * NT + (col >> 3)];
                g_Y[(size_t)row * N + col] = v;
            } else {
                C[(size_t)row * N + col] = v;
            }
        }
    }
}

// Wt[d][k] = U[n, d, r] where k = n*RANK + r
__global__ void transpose_U(const float* __restrict__ U)
{
    int idx = blockIdx.x * 256 + threadIdx.x;   // idx over D_MODEL * NR
    int d = idx >> 9;        // / 512
    int k = idx & (NR - 1);  // % 512
    g_Wt[idx] = U[(size_t)(k >> 3) * (D_MODEL * RANK) + (size_t)d * RANK + (k & 7)];
}

// fro[n] = ||U[n]||_F * ||V[n]||_F / sqrt(D_MODEL*RANK)
__global__ void fro_norms(const float* __restrict__ U, const float* __restrict__ V,
                          float* __restrict__ fro)
{
    __shared__ float ssu[256];
    __shared__ float ssv[256];
    int n = blockIdx.x;
    float su = 0.0f, sv = 0.0f;
    for (int i = threadIdx.x; i < D_MODEL * RANK; i += 256) {
        float u = U[(size_t)n * (D_MODEL * RANK) + i];
        float v = V[(size_t)n * (D_MODEL * RANK) + i];
        su += u * u;
        sv += v * v;
    }
    ssu[threadIdx.x] = su;
    ssv[threadIdx.x] = sv;
    __syncthreads();
    for (int s = 128; s > 0; s >>= 1) {
        if (threadIdx.x < s) {
            ssu[threadIdx.x] += ssu[threadIdx.x + s];
            ssv[threadIdx.x] += ssv[threadIdx.x + s];
        }
        __syncthreads();
    }
    if (threadIdx.x == 0)
        fro[n] = sqrtf(ssu[0]) * sqrtf(ssv[0]) * rsqrtf((float)(D_MODEL * RANK));
}

extern "C" void kernel_launch(void* const* d_in, const int* in_sizes, int n_in,
                              void* d_out, int out_size)
{
    const float* x    = (const float*)d_in[0];   // (4096, 1024)
    const float* V    = (const float*)d_in[1];   // (64, 8, 1024)  == Vflat (512, 1024)
    const float* U    = (const float*)d_in[2];   // (64, 1024, 8)
    const float* enc  = (const float*)d_in[3];   // (64, 1024)
    const float* bias = (const float*)d_in[4];   // (64,)

    float* out  = (float*)d_out;                         // (4096, 1024)
    float* gate = out + (size_t)BATCH * D_MODEL;         // (4096, 64)
    float* fro  = gate + (size_t)BATCH * NT;             // (64,)

    // Phase 1: gate = relu(x @ enc^T - bias)   [4096 x 64, K=1024]
    gemm_nt<128, 64, 16, 8, 4, 0>
        <<<dim3(NT / 64, BATCH / 128), 256>>>(x, enc, gate, BATCH, NT, D_MODEL, bias, nullptr);

    // Transpose U into Wt (independent of phase 1)
    transpose_U<<<(D_MODEL * NR) / 256, 256>>>(U);

    // Phase 2: Y = (x @ Vflat^T) * gate   [4096 x 512, K=1024] -> g_Y
    gemm_nt<128, 128, 16, 8, 8, 1>
        <<<dim3(NR / 128, BATCH / 128), 256>>>(x, V, nullptr, BATCH, NR, D_MODEL, nullptr, gate);

    // Phase 3: out = Y @ Wt^T   [4096 x 1024, K=512]
    gemm_nt<128, 128, 16, 8, 8, 2>
        <<<dim3(D_MODEL / 128, BATCH / 128), 256>>>(nullptr, nullptr, out, BATCH, D_MODEL, NR,
                                                    nullptr, nullptr);

    // Frobenius norms
    fro_norms<<<NT, 256>>>(U, V, fro);
}

// round 2
// speedup vs baseline: 4.2975x; 4.2975x over previous
#include <cuda_runtime.h>
#include <math.h>
#include <stdint.h>

#define BATCH   4096
#define D_MODEL 1024
#define NT      64
#define RANK    8
#define NR      (NT * RANK)   /* 512 */

// Scratch (device globals: no allocation allowed)
__device__ float g_Y[(size_t)BATCH * NR];      // gated Vx, (batch, n*r)
__device__ float g_Wt[(size_t)D_MODEL * NR];   // U transposed: Wt[d][k] = U[n,d,r]

__device__ __forceinline__ uint32_t f2tf32(float f) {
    uint32_t u;
    asm("cvt.rna.tf32.f32 %0, %1;" : "=r"(u) : "f"(f));
    return u;
}

__device__ __forceinline__ void mma_tf32(float c[4], const uint32_t a[4], const uint32_t b[2]) {
    asm volatile(
        "mma.sync.aligned.m16n8k8.row.col.f32.tf32.tf32.f32 "
        "{%0,%1,%2,%3}, {%4,%5,%6,%7}, {%8,%9}, {%0,%1,%2,%3};"
        : "+f"(c[0]), "+f"(c[1]), "+f"(c[2]), "+f"(c[3])
        : "r"(a[0]), "r"(a[1]), "r"(a[2]), "r"(a[3]), "r"(b[0]), "r"(b[1]));
}

// ---------------------------------------------------------------------------
// NT GEMM via tf32 mma.sync: C[M,N] = A[M,K] @ B[N,K]^T
// MODE 0: gate epilogue  v = relu(acc - bias[col])
// MODE 1: scale epilogue v = acc * gate[row*NT + col/8] -> g_Y
// MODE 2: plain          A := g_Y, B := g_Wt
// ---------------------------------------------------------------------------
template <int BM, int BN, int BK, int WY, int WX, int MODE>
__global__ __launch_bounds__(WY * WX * 32)
void gemm_tf32(const float* __restrict__ A, const float* __restrict__ B,
               float* __restrict__ C, int M, int N, int K,
               const float* __restrict__ bias, const float* __restrict__ gate)
{
    constexpr int THREADS = WY * WX * 32;
    constexpr int WM = BM / WY;        // warp tile rows
    constexpr int WN = BN / WX;        // warp tile cols
    constexpr int MI = WM / 16;        // m16 tiles per warp
    constexpr int NI = WN / 8;         // n8 tiles per warp
    constexpr int PAD = 4;

    __shared__ uint32_t As[BM][BK + PAD];
    __shared__ uint32_t Bs[BN][BK + PAD];

    const int tid  = threadIdx.x;
    const int wid  = tid >> 5;
    const int lane = tid & 31;
    const int wy   = wid / WX;
    const int wx   = wid % WX;
    const int lq   = lane >> 2;   // 0..7
    const int lr   = lane & 3;    // 0..3
    const int row0 = blockIdx.y * BM;
    const int col0 = blockIdx.x * BN;

    const float* Aptr = (MODE == 2) ? g_Y  : A;
    const float* Bptr = (MODE == 2) ? g_Wt : B;

    float acc[MI][NI][4];
#pragma unroll
    for (int mi = 0; mi < MI; mi++)
#pragma unroll
        for (int ni = 0; ni < NI; ni++)
#pragma unroll
            for (int j = 0; j < 4; j++) acc[mi][ni][j] = 0.0f;

    for (int k0 = 0; k0 < K; k0 += BK) {
        // ---- load A tile (BM x BK) as tf32, float4-wide ----
        constexpr int A_V4 = BM * BK / 4;
#pragma unroll
        for (int i = tid; i < A_V4; i += THREADS) {
            int r = i / (BK / 4), c4 = i % (BK / 4);
            float4 v = *(const float4*)&Aptr[(size_t)(row0 + r) * K + k0 + c4 * 4];
            uint4 u;
            u.x = f2tf32(v.x); u.y = f2tf32(v.y); u.z = f2tf32(v.z); u.w = f2tf32(v.w);
            *(uint4*)&As[r][c4 * 4] = u;
        }
        // ---- load B tile (BN x BK) ----
        constexpr int B_V4 = BN * BK / 4;
#pragma unroll
        for (int i = tid; i < B_V4; i += THREADS) {
            int r = i / (BK / 4), c4 = i % (BK / 4);
            float4 v = *(const float4*)&Bptr[(size_t)(col0 + r) * K + k0 + c4 * 4];
            uint4 u;
            u.x = f2tf32(v.x); u.y = f2tf32(v.y); u.z = f2tf32(v.z); u.w = f2tf32(v.w);
            *(uint4*)&Bs[r][c4 * 4] = u;
        }
        __syncthreads();

#pragma unroll
        for (int kk = 0; kk < BK; kk += 8) {
            uint32_t af[MI][4], bf[NI][2];
#pragma unroll
            for (int mi = 0; mi < MI; mi++) {
                int r = wy * WM + mi * 16 + lq;
                af[mi][0] = As[r][kk + lr];
                af[mi][1] = As[r + 8][kk + lr];
                af[mi][2] = As[r][kk + lr + 4];
                af[mi][3] = As[r + 8][kk + lr + 4];
            }
#pragma unroll
            for (int ni = 0; ni < NI; ni++) {
                int c = wx * WN + ni * 8 + lq;
                bf[ni][0] = Bs[c][kk + lr];
                bf[ni][1] = Bs[c][kk + lr + 4];
            }
#pragma unroll
            for (int mi = 0; mi < MI; mi++)
#pragma unroll
                for (int ni = 0; ni < NI; ni++)
                    mma_tf32(acc[mi][ni], af[mi], bf[ni]);
        }
        __syncthreads();
    }

    // ---- epilogue ----
#pragma unroll
    for (int mi = 0; mi < MI; mi++) {
        int r0 = row0 + wy * WM + mi * 16 + lq;   // rows r0 and r0+8
#pragma unroll
        for (int ni = 0; ni < NI; ni++) {
            int c = col0 + wx * WN + ni * 8 + 2 * lr;
            float v0 = acc[mi][ni][0], v1 = acc[mi][ni][1];
            float v2 = acc[mi][ni][2], v3 = acc[mi][ni][3];
            if constexpr (MODE == 0) {
                float b0 = bias[c], b1 = bias[c + 1];
                v0 -= b0; v1 -= b1; v2 -= b0; v3 -= b1;
                v0 = v0 > 0.f ? v0 : 0.f;  v1 = v1 > 0.f ? v1 : 0.f;
                v2 = v2 > 0.f ? v2 : 0.f;  v3 = v3 > 0.f ? v3 : 0.f;
                *(float2*)&C[(size_t)r0 * N + c]       = make_float2(v0, v1);
                *(float2*)&C[(size_t)(r0 + 8) * N + c] = make_float2(v2, v3);
            } else if constexpr (MODE == 1) {
                int gc = (col0 + wx * WN + ni * 8) >> 3;
                float g0 = gate[(size_t)r0 * NT + gc];
                float g1 = gate[(size_t)(r0 + 8) * NT + gc];
                *(float2*)&g_Y[(size_t)r0 * N + c]       = make_float2(v0 * g0, v1 * g0);
                *(float2*)&g_Y[(size_t)(r0 + 8) * N + c] = make_float2(v2 * g1, v3 * g1);
            } else {
                *(float2*)&C[(size_t)r0 * N + c]       = make_float2(v0, v1);
                *(float2*)&C[(size_t)(r0 + 8) * N + c] = make_float2(v2, v3);
            }
        }
    }
}

// Wt[d][k] = U[n, d, r] where k = n*RANK + r
__global__ void transpose_U(const float* __restrict__ U)
{
    int idx = blockIdx.x * 256 + threadIdx.x;
    int d = idx >> 9;
    int k = idx & (NR - 1);
    g_Wt[idx] = U[(size_t)(k >> 3) * (D_MODEL * RANK) + (size_t)d * RANK + (k & 7)];
}

__global__ void fro_norms(const float* __restrict__ U, const float* __restrict__ V,
                          float* __restrict__ fro)
{
    __shared__ float ssu[256];
    __shared__ float ssv[256];
    int n = blockIdx.x;
    float su = 0.0f, sv = 0.0f;
    for (int i = threadIdx.x; i < D_MODEL * RANK; i += 256) {
        float u = U[(size_t)n * (D_MODEL * RANK) + i];
        float v = V[(size_t)n * (D_MODEL * RANK) + i];
        su += u * u;
        sv += v * v;
    }
    ssu[threadIdx.x] = su;
    ssv[threadIdx.x] = sv;
    __syncthreads();
    for (int s = 128; s > 0; s >>= 1) {
        if (threadIdx.x < s) {
            ssu[threadIdx.x] += ssu[threadIdx.x + s];
            ssv[threadIdx.x] += ssv[threadIdx.x + s];
        }
        __syncthreads();
    }
    if (threadIdx.x == 0)
        fro[n] = sqrtf(ssu[0]) * sqrtf(ssv[0]) * rsqrtf((float)(D_MODEL * RANK));
}

extern "C" void kernel_launch(void* const* d_in, const int* in_sizes, int n_in,
                              void* d_out, int out_size)
{
    const float* x    = (const float*)d_in[0];
    const float* V    = (const float*)d_in[1];
    const float* U    = (const float*)d_in[2];
    const float* enc  = (const float*)d_in[3];
    const float* bias = (const float*)d_in[4];

    float* out  = (float*)d_out;
    float* gate = out + (size_t)BATCH * D_MODEL;
    float* fro  = gate + (size_t)BATCH * NT;

    // Phase 1: gate = relu(x @ enc^T - bias)   [4096 x 64, K=1024]
    gemm_tf32<128, 64, 32, 2, 4, 0>
        <<<dim3(1, BATCH / 128), 256>>>(x, enc, gate, BATCH, NT, D_MODEL, bias, nullptr);

    // Transpose U into Wt (independent of phase 1)
    transpose_U<<<(D_MODEL * NR) / 256, 256>>>(U);

    // Phase 2: Y = (x @ Vflat^T) * gate   [4096 x 512, K=1024] -> g_Y
    gemm_tf32<128, 128, 32, 2, 4, 1>
        <<<dim3(NR / 128, BATCH / 128), 256>>>(x, V, nullptr, BATCH, NR, D_MODEL, nullptr, gate);

    // Phase 3: out = Y @ Wt^T   [4096 x 1024, K=512]
    gemm_tf32<128, 128, 32, 2, 4, 2>
        <<<dim3(D_MODEL / 128, BATCH / 128), 256>>>(nullptr, nullptr, out, BATCH, D_MODEL, NR,
                                                    nullptr, nullptr);

    fro_norms<<<NT, 256>>>(U, V, fro);
}